// round 1
// baseline (speedup 1.0000x reference)
#include <cuda_runtime.h>

// CategorySpecificLinear: out[b] = x[b] @ W[cat_ids[b]] + bias[cat_ids[b]]
// x:   [64, 256, 1024] f32
// cat: [64] i32
// W:   [32, 1024, 2048] f32
// b:   [32, 2048] f32
// out: [64, 256, 2048] f32
//
// Round 0: SIMT tiled GEMM, 128x128x16 tiles, packed fma.rn.f32x2 inner loop.

#define B_DIM   64
#define T_DIM   256
#define K_DIM   1024
#define N_DIM   2048

#define TM 128
#define TN 128
#define TK 16

__global__ void __launch_bounds__(256, 2)
cat_linear_kernel(const float* __restrict__ x,
                  const int*   __restrict__ cat_ids,
                  const float* __restrict__ W,
                  const float* __restrict__ bias,
                  float*       __restrict__ out)
{
    // A stored transposed (k-major) with pad to dodge store conflicts.
    __shared__ float As[2][TK][TM + 4];   // 132 floats/row, 528B (16B-aligned rows)
    __shared__ float Bs[2][TK][TN];

    const int tid   = threadIdx.x;
    const int bn    = blockIdx.x;   // N tile: 0..15
    const int bm    = blockIdx.y;   // M tile: 0..1
    const int batch = blockIdx.z;   // 0..63

    const int c = cat_ids[batch];

    const float* A = x + (size_t)batch * T_DIM * K_DIM + (size_t)bm * TM * K_DIM;
    const float* Bp = W + (size_t)c * K_DIM * N_DIM + (size_t)bn * TN;

    // ---- load index mapping ----
    // A tile: 128 rows x 16 cols -> 512 float4; thread loads rows ar, ar+64 at k-offset ac4
    const int ar  = tid >> 2;          // 0..63
    const int ac4 = (tid & 3) * 4;     // 0,4,8,12
    // B tile: 16 rows x 128 cols -> 512 float4; thread loads rows br, br+8 at col bc4
    const int br  = tid >> 5;          // 0..7
    const int bc4 = (tid & 31) * 4;    // 0..124

    // ---- compute mapping: 16x16 thread grid, 8x8 microtile ----
    const int tr = (tid >> 4) * 8;     // row offset within tile
    const int tc = (tid & 15) * 8;     // col offset within tile

    // accumulators as packed f32x2 (8 rows x 4 col-pairs)
    unsigned long long acc[8][4];
    #pragma unroll
    for (int i = 0; i < 8; i++)
        #pragma unroll
        for (int j = 0; j < 4; j++)
            acc[i][j] = 0ull;

    // ---- prologue: load first k-tile into buffer 0 ----
    {
        #pragma unroll
        for (int rr = 0; rr < 2; rr++) {
            int r = ar + rr * 64;
            float4 v = *(const float4*)(A + (size_t)r * K_DIM + ac4);
            As[0][ac4 + 0][r] = v.x;
            As[0][ac4 + 1][r] = v.y;
            As[0][ac4 + 2][r] = v.z;
            As[0][ac4 + 3][r] = v.w;
        }
        #pragma unroll
        for (int rr = 0; rr < 2; rr++) {
            int r = br + rr * 8;
            float4 v = *(const float4*)(Bp + (size_t)r * N_DIM + bc4);
            *(float4*)&Bs[0][r][bc4] = v;
        }
    }
    __syncthreads();

    int buf = 0;
    for (int k0 = 0; k0 < K_DIM; k0 += TK) {
        const int nbuf = buf ^ 1;
        const bool has_next = (k0 + TK) < K_DIM;

        // issue next-tile global loads into registers (latency hidden by compute)
        float4 pa[2], pb[2];
        if (has_next) {
            #pragma unroll
            for (int rr = 0; rr < 2; rr++) {
                int r = ar + rr * 64;
                pa[rr] = *(const float4*)(A + (size_t)r * K_DIM + (k0 + TK) + ac4);
            }
            #pragma unroll
            for (int rr = 0; rr < 2; rr++) {
                int r = br + rr * 8;
                pb[rr] = *(const float4*)(Bp + (size_t)(k0 + TK + r) * N_DIM + bc4);
            }
        }

        // ---- compute on current buffer ----
        #pragma unroll
        for (int k = 0; k < TK; k++) {
            float a[8];
            *(float4*)&a[0] = *(const float4*)&As[buf][k][tr];
            *(float4*)&a[4] = *(const float4*)&As[buf][k][tr + 4];

            unsigned long long b2[4];
            {
                ulonglong2 bb0 = *(const ulonglong2*)&Bs[buf][k][tc];
                ulonglong2 bb1 = *(const ulonglong2*)&Bs[buf][k][tc + 4];
                b2[0] = bb0.x; b2[1] = bb0.y; b2[2] = bb1.x; b2[3] = bb1.y;
            }

            #pragma unroll
            for (int i = 0; i < 8; i++) {
                unsigned long long a2;
                asm("mov.b64 %0, {%1, %1};" : "=l"(a2) : "f"(a[i]));
                #pragma unroll
                for (int j = 0; j < 4; j++) {
                    asm("fma.rn.f32x2 %0, %1, %2, %0;"
                        : "+l"(acc[i][j]) : "l"(a2), "l"(b2[j]));
                }
            }
        }

        // ---- stage next tile into smem ----
        if (has_next) {
            #pragma unroll
            for (int rr = 0; rr < 2; rr++) {
                int r = ar + rr * 64;
                As[nbuf][ac4 + 0][r] = pa[rr].x;
                As[nbuf][ac4 + 1][r] = pa[rr].y;
                As[nbuf][ac4 + 2][r] = pa[rr].z;
                As[nbuf][ac4 + 3][r] = pa[rr].w;
            }
            #pragma unroll
            for (int rr = 0; rr < 2; rr++) {
                int r = br + rr * 8;
                *(float4*)&Bs[nbuf][r][bc4] = pb[rr];
            }
        }
        __syncthreads();
        buf = nbuf;
    }

    // ---- epilogue: unpack, add bias, store ----
    float bfr[8];
    {
        const float* bv = bias + (size_t)c * N_DIM + (size_t)bn * TN + tc;
        *(float4*)&bfr[0] = *(const float4*)(bv);
        *(float4*)&bfr[4] = *(const float4*)(bv + 4);
    }

    float* o = out + (size_t)batch * T_DIM * N_DIM
                   + (size_t)(bm * TM + tr) * N_DIM
                   + (size_t)bn * TN + tc;

    #pragma unroll
    for (int i = 0; i < 8; i++) {
        float v[8];
        #pragma unroll
        for (int j = 0; j < 4; j++) {
            float lo, hi;
            asm("mov.b64 {%0, %1}, %2;" : "=f"(lo), "=f"(hi) : "l"(acc[i][j]));
            v[2 * j]     = lo + bfr[2 * j];
            v[2 * j + 1] = hi + bfr[2 * j + 1];
        }
        *(float4*)(o + (size_t)i * N_DIM)     = *(float4*)&v[0];
        *(float4*)(o + (size_t)i * N_DIM + 4) = *(float4*)&v[4];
    }
}

extern "C" void kernel_launch(void* const* d_in, const int* in_sizes, int n_in,
                              void* d_out, int out_size)
{
    const float* x       = (const float*)d_in[0];
    const int*   cat_ids = (const int*)  d_in[1];
    const float* W       = (const float*)d_in[2];
    const float* bias    = (const float*)d_in[3];
    float*       out     = (float*)d_out;

    dim3 grid(N_DIM / TN, T_DIM / TM, B_DIM);  // (16, 2, 64)
    dim3 block(256);
    cat_linear_kernel<<<grid, block>>>(x, cat_ids, W, bias, out);
}

// round 3
// speedup vs baseline: 2.4571x; 2.4571x over previous
#include <cuda_runtime.h>
#include <cstdint>

// CategorySpecificLinear via mma.sync tf32 (sm_80 baseline ISA — tcgen05 is
// unavailable: harness compiles PTX at compute_103, which rejects all
// sm_103a-suffix instructions).
//
// out[b] = x[b] @ W[cat_ids[b]] + bias[cat_ids[b]]
// x: [64,256,1024] f32   W: [32,1024,2048] f32   bias: [32,2048]   out: [64,256,2048]

#define B_DIM 64
#define T_DIM 256
#define K_DIM 1024
#define N_DIM 2048

#define TM 128
#define TN 128
#define TK 32
#define STAGES (K_DIM / TK)      // 32

#define ASTRIDE 36               // 32 k + 4 pad (floats)  -> conflict-free frag LDS
#define BSTRIDE 136              // 128 n + 8 pad (floats) -> conflict-free frag LDS
#define A_FLOATS (TM * ASTRIDE)  // 4608
#define B_FLOATS (TK * BSTRIDE)  // 4352
#define STAGE_FLOATS (A_FLOATS + B_FLOATS)   // 8960
#define SMEM_BYTES (2 * STAGE_FLOATS * 4)    // 71680

static __device__ __forceinline__ uint32_t f2tf32(float f) {
    uint32_t r; asm("cvt.rna.tf32.f32 %0, %1;" : "=r"(r) : "f"(f)); return r;
}

static __device__ __forceinline__ void mma_tf32(float (&d)[4],
                                                const uint32_t (&a)[4],
                                                const uint32_t (&b)[2]) {
    asm volatile(
        "mma.sync.aligned.m16n8k8.row.col.f32.tf32.tf32.f32 "
        "{%0,%1,%2,%3}, {%4,%5,%6,%7}, {%8,%9}, {%0,%1,%2,%3};"
        : "+f"(d[0]), "+f"(d[1]), "+f"(d[2]), "+f"(d[3])
        : "r"(a[0]), "r"(a[1]), "r"(a[2]), "r"(a[3]), "r"(b[0]), "r"(b[1]));
}

__global__ void __launch_bounds__(256, 1)
cat_linear_mma(const float* __restrict__ x, const int* __restrict__ cat_ids,
               const float* __restrict__ W, const float* __restrict__ bias,
               float* __restrict__ out)
{
    extern __shared__ float sm[];

    const int tid  = threadIdx.x;
    const int wid  = tid >> 5;
    const int lane = tid & 31;
    const int wm   = wid >> 2;        // 0..1  (M half)
    const int wn   = wid & 3;         // 0..3  (N quarter)
    const int fr   = lane >> 2;       // 0..7  frag row
    const int fc   = lane & 3;        // 0..3  frag col

    const int bn    = blockIdx.x;     // 0..15
    const int bm    = blockIdx.y;     // 0..1
    const int batch = blockIdx.z;     // 0..63
    const int n0    = bn * TN;
    const int cat   = cat_ids[batch];

    const float* Ap = x + (size_t)batch * T_DIM * K_DIM + (size_t)bm * TM * K_DIM;
    const float* Wp = W + (size_t)cat * K_DIM * N_DIM + n0;

    // staging index precompute (4 float4 each for A and B per thread)
    int a_row[4], a_kc[4], b_k[4], b_n4[4];
#pragma unroll
    for (int i = 0; i < 4; i++) {
        int f = tid + 256 * i;
        a_row[i] = f >> 3;            // 0..127
        a_kc[i]  = (f & 7) * 4;       // 0..28
        b_k[i]   = f >> 5;            // 0..31
        b_n4[i]  = (f & 31) * 4;      // 0..124
    }

    float acc[4][4][4];
#pragma unroll
    for (int m = 0; m < 4; m++)
#pragma unroll
        for (int n = 0; n < 4; n++)
#pragma unroll
            for (int j = 0; j < 4; j++) acc[m][n][j] = 0.f;

    float4 pa[4], pb[4];

    // ---- prologue: load + stage k-tile 0 into buffer 0 ----
#pragma unroll
    for (int i = 0; i < 4; i++) {
        pa[i] = *(const float4*)(Ap + (size_t)a_row[i] * K_DIM + a_kc[i]);
        pb[i] = *(const float4*)(Wp + (size_t)b_k[i] * N_DIM + b_n4[i]);
    }
    {
        float* As = sm;
        float* Bs = sm + A_FLOATS;
#pragma unroll
        for (int i = 0; i < 4; i++) {
            float* p = As + a_row[i] * ASTRIDE + a_kc[i];
            p[0] = __uint_as_float(f2tf32(pa[i].x));
            p[1] = __uint_as_float(f2tf32(pa[i].y));
            p[2] = __uint_as_float(f2tf32(pa[i].z));
            p[3] = __uint_as_float(f2tf32(pa[i].w));
            float* q = Bs + b_k[i] * BSTRIDE + b_n4[i];
            q[0] = __uint_as_float(f2tf32(pb[i].x));
            q[1] = __uint_as_float(f2tf32(pb[i].y));
            q[2] = __uint_as_float(f2tf32(pb[i].z));
            q[3] = __uint_as_float(f2tf32(pb[i].w));
        }
    }
    __syncthreads();

    for (int s = 0; s < STAGES; s++) {
        // prefetch next k-tile into registers (overlaps the MMAs below)
        if (s + 1 < STAGES) {
            const int k0 = (s + 1) * TK;
#pragma unroll
            for (int i = 0; i < 4; i++) {
                pa[i] = *(const float4*)(Ap + (size_t)a_row[i] * K_DIM + k0 + a_kc[i]);
                pb[i] = *(const float4*)(Wp + (size_t)(k0 + b_k[i]) * N_DIM + b_n4[i]);
            }
        }

        // ---- compute on buffer s&1 ----
        {
            const float* As = sm + (s & 1) * STAGE_FLOATS;
            const float* Bs = As + A_FLOATS;
#pragma unroll
            for (int kk = 0; kk < TK; kk += 8) {
                uint32_t af[4][4], bf[4][2];
#pragma unroll
                for (int m = 0; m < 4; m++) {
                    const float* ap = As + (wm * 64 + m * 16 + fr) * ASTRIDE + kk + fc;
                    af[m][0] = __float_as_uint(ap[0]);
                    af[m][1] = __float_as_uint(ap[8 * ASTRIDE]);
                    af[m][2] = __float_as_uint(ap[4]);
                    af[m][3] = __float_as_uint(ap[8 * ASTRIDE + 4]);
                }
#pragma unroll
                for (int n = 0; n < 4; n++) {
                    const float* bp = Bs + (kk + fc) * BSTRIDE + wn * 32 + n * 8 + fr;
                    bf[n][0] = __float_as_uint(bp[0]);
                    bf[n][1] = __float_as_uint(bp[4 * BSTRIDE]);
                }
#pragma unroll
                for (int m = 0; m < 4; m++)
#pragma unroll
                    for (int n = 0; n < 4; n++)
                        mma_tf32(acc[m][n], af[m], bf[n]);
            }
        }

        // ---- stage next tile into the other buffer ----
        if (s + 1 < STAGES) {
            float* As = sm + ((s + 1) & 1) * STAGE_FLOATS;
            float* Bs = As + A_FLOATS;
#pragma unroll
            for (int i = 0; i < 4; i++) {
                float* p = As + a_row[i] * ASTRIDE + a_kc[i];
                p[0] = __uint_as_float(f2tf32(pa[i].x));
                p[1] = __uint_as_float(f2tf32(pa[i].y));
                p[2] = __uint_as_float(f2tf32(pa[i].z));
                p[3] = __uint_as_float(f2tf32(pa[i].w));
                float* q = Bs + b_k[i] * BSTRIDE + b_n4[i];
                q[0] = __uint_as_float(f2tf32(pb[i].x));
                q[1] = __uint_as_float(f2tf32(pb[i].y));
                q[2] = __uint_as_float(f2tf32(pb[i].z));
                q[3] = __uint_as_float(f2tf32(pb[i].w));
            }
        }
        __syncthreads();
    }

    // ---- epilogue: add bias, store ----
    {
        const float* brow = bias + (size_t)cat * N_DIM;
        float* obase = out + (size_t)batch * T_DIM * N_DIM;
#pragma unroll
        for (int m = 0; m < 4; m++) {
            int row = bm * TM + wm * 64 + m * 16 + fr;
#pragma unroll
            for (int n = 0; n < 4; n++) {
                int col = n0 + wn * 32 + n * 8 + fc * 2;
                float2 bv = *(const float2*)(brow + col);
                float2 o0, o1;
                o0.x = acc[m][n][0] + bv.x;
                o0.y = acc[m][n][1] + bv.y;
                o1.x = acc[m][n][2] + bv.x;
                o1.y = acc[m][n][3] + bv.y;
                *(float2*)(obase + (size_t)row * N_DIM + col)       = o0;
                *(float2*)(obase + (size_t)(row + 8) * N_DIM + col) = o1;
            }
        }
    }
}

extern "C" void kernel_launch(void* const* d_in, const int* in_sizes, int n_in,
                              void* d_out, int out_size)
{
    const float* x       = (const float*)d_in[0];
    const int*   cat_ids = (const int*)  d_in[1];
    const float* W       = (const float*)d_in[2];
    const float* bias    = (const float*)d_in[3];
    float*       out     = (float*)d_out;

    cudaFuncSetAttribute(cat_linear_mma, cudaFuncAttributeMaxDynamicSharedMemorySize, SMEM_BYTES);
    dim3 grid(N_DIM / TN, T_DIM / TM, B_DIM);   // (16, 2, 64)
    cat_linear_mma<<<grid, 256, SMEM_BYTES>>>(x, cat_ids, W, bias, out);
}

// round 4
// speedup vs baseline: 3.0129x; 1.2262x over previous
#include <cuda_runtime.h>
#include <cstdint>

// CategorySpecificLinear via mma.sync tf32 + 3-stage cp.async pipeline.
// out[b] = x[b] @ W[cat_ids[b]] + bias[cat_ids[b]]
// x: [64,256,1024] f32   W: [32,1024,2048] f32   bias: [32,2048]   out: [64,256,2048]

#define B_DIM 64
#define T_DIM 256
#define K_DIM 1024
#define N_DIM 2048

#define TM 128
#define TN 128
#define TK 32
#define STAGES (K_DIM / TK)      // 32
#define NBUF 3

#define ASTRIDE 36               // 32 k + 4 pad (floats); 144B row, 16B-aligned
#define BSTRIDE 136              // 128 n + 8 pad (floats); 544B row, 16B-aligned
#define A_FLOATS (TM * ASTRIDE)  // 4608
#define B_FLOATS (TK * BSTRIDE)  // 4352
#define STAGE_FLOATS (A_FLOATS + B_FLOATS)     // 8960 (35840 B)
#define SMEM_BYTES (NBUF * STAGE_FLOATS * 4)   // 107520

static __device__ __forceinline__ uint32_t f2tf32(float f) {
    uint32_t r; asm("cvt.rna.tf32.f32 %0, %1;" : "=r"(r) : "f"(f)); return r;
}

static __device__ __forceinline__ void cpasync16(uint32_t dst, const void* src) {
    asm volatile("cp.async.cg.shared.global [%0], [%1], 16;" :: "r"(dst), "l"(src));
}

static __device__ __forceinline__ void mma_tf32(float (&d)[4],
                                                const uint32_t (&a)[4],
                                                const uint32_t (&b)[2]) {
    asm volatile(
        "mma.sync.aligned.m16n8k8.row.col.f32.tf32.tf32.f32 "
        "{%0,%1,%2,%3}, {%4,%5,%6,%7}, {%8,%9}, {%0,%1,%2,%3};"
        : "+f"(d[0]), "+f"(d[1]), "+f"(d[2]), "+f"(d[3])
        : "r"(a[0]), "r"(a[1]), "r"(a[2]), "r"(a[3]), "r"(b[0]), "r"(b[1]));
}

__global__ void __launch_bounds__(256, 2)
cat_linear_mma(const float* __restrict__ x, const int* __restrict__ cat_ids,
               const float* __restrict__ W, const float* __restrict__ bias,
               float* __restrict__ out)
{
    extern __shared__ float sm[];
    const uint32_t smbase = (uint32_t)__cvta_generic_to_shared(sm);

    const int tid  = threadIdx.x;
    const int wid  = tid >> 5;
    const int lane = tid & 31;
    const int wm   = wid >> 2;        // 0..1  (M half)
    const int wn   = wid & 3;         // 0..3  (N quarter)
    const int fr   = lane >> 2;       // 0..7  frag row
    const int fc   = lane & 3;        // 0..3  frag col

    const int bn    = blockIdx.x;     // 0..15
    const int bm    = blockIdx.y;     // 0..1
    const int batch = blockIdx.z;     // 0..63
    const int n0    = bn * TN;
    const int cat   = cat_ids[batch];

    const float* Ap = x + (size_t)batch * T_DIM * K_DIM + (size_t)bm * TM * K_DIM;
    const float* Wp = W + (size_t)cat * K_DIM * N_DIM + n0;

    // per-thread load mapping: 4 float4 chunks for A, 4 for B per stage
    const int a_row = tid >> 1;                 // two threads per A row... no:
    // A: 128 rows x 8 chunks = 1024 chunks; thread covers chunks tid, tid+256, ...
    // B: 32 rows x 32 chunks = 1024 chunks likewise.
    int ar[4], ac[4], bk[4], bc[4];
#pragma unroll
    for (int i = 0; i < 4; i++) {
        int f = tid + 256 * i;
        ar[i] = f >> 3;            // 0..127
        ac[i] = (f & 7) * 4;       // k offset 0..28
        bk[i] = f >> 5;            // 0..31
        bc[i] = (f & 31) * 4;      // n offset 0..124
    }

    float acc[4][4][4];
#pragma unroll
    for (int m = 0; m < 4; m++)
#pragma unroll
        for (int n = 0; n < 4; n++)
#pragma unroll
            for (int j = 0; j < 4; j++) acc[m][n][j] = 0.f;

    // ---- issue one stage's cp.asyncs into buffer `buf` ----
    auto issue_stage = [&](int s, int buf) {
        const uint32_t abase = smbase + (uint32_t)(buf * STAGE_FLOATS) * 4u;
        const uint32_t bbase = abase + (uint32_t)A_FLOATS * 4u;
        const int k0 = s * TK;
#pragma unroll
        for (int i = 0; i < 4; i++)
            cpasync16(abase + (uint32_t)(ar[i] * ASTRIDE + ac[i]) * 4u,
                      Ap + (size_t)ar[i] * K_DIM + k0 + ac[i]);
#pragma unroll
        for (int i = 0; i < 4; i++)
            cpasync16(bbase + (uint32_t)(bk[i] * BSTRIDE + bc[i]) * 4u,
                      Wp + (size_t)(k0 + bk[i]) * N_DIM + bc[i]);
    };

    // ---- prologue: stages 0 and 1 in flight ----
    issue_stage(0, 0);
    asm volatile("cp.async.commit_group;" ::: "memory");
    issue_stage(1, 1);
    asm volatile("cp.async.commit_group;" ::: "memory");

    for (int s = 0; s < STAGES; s++) {
        // group s complete when <=1 newer groups pending (tail uses empty groups)
        asm volatile("cp.async.wait_group 1;" ::: "memory");
        __syncthreads();

        // refill: buf (s+2)%3 held stage s-1, finished by all warps at the barrier
        if (s + 2 < STAGES)
            issue_stage(s + 2, (s + 2) % NBUF);
        asm volatile("cp.async.commit_group;" ::: "memory");

        // ---- compute on buffer s%3 (fp32 in smem, cvt to tf32 at frag load) ----
        const float* As = sm + (s % NBUF) * STAGE_FLOATS;
        const float* Bs = As + A_FLOATS;
#pragma unroll
        for (int kk = 0; kk < TK; kk += 8) {
            uint32_t af[4][4], bf[4][2];
#pragma unroll
            for (int m = 0; m < 4; m++) {
                const float* ap = As + (wm * 64 + m * 16 + fr) * ASTRIDE + kk + fc;
                af[m][0] = f2tf32(ap[0]);
                af[m][1] = f2tf32(ap[8 * ASTRIDE]);
                af[m][2] = f2tf32(ap[4]);
                af[m][3] = f2tf32(ap[8 * ASTRIDE + 4]);
            }
#pragma unroll
            for (int n = 0; n < 4; n++) {
                const float* bp = Bs + (kk + fc) * BSTRIDE + wn * 32 + n * 8 + fr;
                bf[n][0] = f2tf32(bp[0]);
                bf[n][1] = f2tf32(bp[4 * BSTRIDE]);
            }
#pragma unroll
            for (int m = 0; m < 4; m++)
#pragma unroll
                for (int n = 0; n < 4; n++)
                    mma_tf32(acc[m][n], af[m], bf[n]);
        }
    }

    // ---- epilogue: add bias, store ----
    {
        const float* brow = bias + (size_t)cat * N_DIM;
        float* obase = out + (size_t)batch * T_DIM * N_DIM;
#pragma unroll
        for (int m = 0; m < 4; m++) {
            int row = bm * TM + wm * 64 + m * 16 + fr;
#pragma unroll
            for (int n = 0; n < 4; n++) {
                int col = n0 + wn * 32 + n * 8 + fc * 2;
                float2 bv = *(const float2*)(brow + col);
                float2 o0, o1;
                o0.x = acc[m][n][0] + bv.x;
                o0.y = acc[m][n][1] + bv.y;
                o1.x = acc[m][n][2] + bv.x;
                o1.y = acc[m][n][3] + bv.y;
                *(float2*)(obase + (size_t)row * N_DIM + col)       = o0;
                *(float2*)(obase + (size_t)(row + 8) * N_DIM + col) = o1;
            }
        }
    }
}

extern "C" void kernel_launch(void* const* d_in, const int* in_sizes, int n_in,
                              void* d_out, int out_size)
{
    const float* x       = (const float*)d_in[0];
    const int*   cat_ids = (const int*)  d_in[1];
    const float* W       = (const float*)d_in[2];
    const float* bias    = (const float*)d_in[3];
    float*       out     = (float*)d_out;

    cudaFuncSetAttribute(cat_linear_mma, cudaFuncAttributeMaxDynamicSharedMemorySize, SMEM_BYTES);
    dim3 grid(N_DIM / TN, T_DIM / TM, B_DIM);   // (16, 2, 64)
    cat_linear_mma<<<grid, 256, SMEM_BYTES>>>(x, cat_ids, W, bias, out);
}

// round 5
// speedup vs baseline: 3.1746x; 1.0537x over previous
#include <cuda_runtime.h>
#include <cstdint>

// CategorySpecificLinear via mma.sync tf32 + 3-stage cp.async pipeline.
// Round 5: 4 warps/CTA, 64x64 warp tiles -> halve smem crossbar traffic.
// out[b] = x[b] @ W[cat_ids[b]] + bias[cat_ids[b]]

#define B_DIM 64
#define T_DIM 256
#define K_DIM 1024
#define N_DIM 2048

#define TM 128
#define TN 128
#define TK 32
#define STAGES (K_DIM / TK)      // 32
#define NBUF 3
#define NTHREADS 128

#define ASTRIDE 36               // 32 k + 4 pad (floats)
#define BSTRIDE 136              // 128 n + 8 pad (floats)
#define A_FLOATS (TM * ASTRIDE)  // 4608
#define B_FLOATS (TK * BSTRIDE)  // 4352
#define STAGE_FLOATS (A_FLOATS + B_FLOATS)     // 8960 (35840 B)
#define SMEM_BYTES (NBUF * STAGE_FLOATS * 4)   // 107520

static __device__ __forceinline__ uint32_t f2tf32(float f) {
    uint32_t r; asm("cvt.rna.tf32.f32 %0, %1;" : "=r"(r) : "f"(f)); return r;
}

static __device__ __forceinline__ void cpasync16(uint32_t dst, const void* src) {
    asm volatile("cp.async.cg.shared.global [%0], [%1], 16;" :: "r"(dst), "l"(src));
}

static __device__ __forceinline__ void mma_tf32(float (&d)[4],
                                                const uint32_t (&a)[4],
                                                const uint32_t (&b)[2]) {
    asm volatile(
        "mma.sync.aligned.m16n8k8.row.col.f32.tf32.tf32.f32 "
        "{%0,%1,%2,%3}, {%4,%5,%6,%7}, {%8,%9}, {%0,%1,%2,%3};"
        : "+f"(d[0]), "+f"(d[1]), "+f"(d[2]), "+f"(d[3])
        : "r"(a[0]), "r"(a[1]), "r"(a[2]), "r"(a[3]), "r"(b[0]), "r"(b[1]));
}

__global__ void __launch_bounds__(NTHREADS, 2)
cat_linear_mma(const float* __restrict__ x, const int* __restrict__ cat_ids,
               const float* __restrict__ W, const float* __restrict__ bias,
               float* __restrict__ out)
{
    extern __shared__ float sm[];
    const uint32_t smbase = (uint32_t)__cvta_generic_to_shared(sm);

    const int tid  = threadIdx.x;
    const int wid  = tid >> 5;
    const int lane = tid & 31;
    const int wm   = wid >> 1;        // 0..1  (M half)
    const int wn   = wid & 1;         // 0..1  (N half)
    const int fr   = lane >> 2;       // 0..7
    const int fc   = lane & 3;        // 0..3

    const int bn    = blockIdx.x;     // 0..15
    const int bm    = blockIdx.y;     // 0..1
    const int batch = blockIdx.z;     // 0..63
    const int n0    = bn * TN;
    const int cat   = cat_ids[batch];

    const float* Ap = x + (size_t)batch * T_DIM * K_DIM + (size_t)bm * TM * K_DIM;
    const float* Wp = W + (size_t)cat * K_DIM * N_DIM + n0;

    // cp.async mapping: 1024 chunks for A and for B, 8 each per thread
    int ar[8], ac[8], bk[8], bc[8];
#pragma unroll
    for (int i = 0; i < 8; i++) {
        int f = tid + NTHREADS * i;
        ar[i] = f >> 3;            // 0..127
        ac[i] = (f & 7) * 4;       // 0..28
        bk[i] = f >> 5;            // 0..31
        bc[i] = (f & 31) * 4;      // 0..124
    }

    float acc[4][8][4];
#pragma unroll
    for (int m = 0; m < 4; m++)
#pragma unroll
        for (int n = 0; n < 8; n++)
#pragma unroll
            for (int j = 0; j < 4; j++) acc[m][n][j] = 0.f;

    auto issue_stage = [&](int s, int buf) {
        const uint32_t abase = smbase + (uint32_t)(buf * STAGE_FLOATS) * 4u;
        const uint32_t bbase = abase + (uint32_t)A_FLOATS * 4u;
        const int k0 = s * TK;
#pragma unroll
        for (int i = 0; i < 8; i++)
            cpasync16(abase + (uint32_t)(ar[i] * ASTRIDE + ac[i]) * 4u,
                      Ap + (size_t)ar[i] * K_DIM + k0 + ac[i]);
#pragma unroll
        for (int i = 0; i < 8; i++)
            cpasync16(bbase + (uint32_t)(bk[i] * BSTRIDE + bc[i]) * 4u,
                      Wp + (size_t)(k0 + bk[i]) * N_DIM + bc[i]);
    };

    // prologue: stages 0,1 in flight
    issue_stage(0, 0);
    asm volatile("cp.async.commit_group;" ::: "memory");
    issue_stage(1, 1);
    asm volatile("cp.async.commit_group;" ::: "memory");

    for (int s = 0; s < STAGES; s++) {
        asm volatile("cp.async.wait_group 1;" ::: "memory");
        __syncthreads();

        if (s + 2 < STAGES)
            issue_stage(s + 2, (s + 2) % NBUF);
        asm volatile("cp.async.commit_group;" ::: "memory");

        const float* As = sm + (s % NBUF) * STAGE_FLOATS;
        const float* Bs = As + A_FLOATS;
#pragma unroll
        for (int kk = 0; kk < TK; kk += 8) {
            uint32_t af[4][4], bf[8][2];
#pragma unroll
            for (int m = 0; m < 4; m++) {
                const float* ap = As + (wm * 64 + m * 16 + fr) * ASTRIDE + kk + fc;
                af[m][0] = f2tf32(ap[0]);
                af[m][1] = f2tf32(ap[8 * ASTRIDE]);
                af[m][2] = f2tf32(ap[4]);
                af[m][3] = f2tf32(ap[8 * ASTRIDE + 4]);
            }
#pragma unroll
            for (int n = 0; n < 8; n++) {
                const float* bp = Bs + (kk + fc) * BSTRIDE + wn * 64 + n * 8 + fr;
                bf[n][0] = f2tf32(bp[0]);
                bf[n][1] = f2tf32(bp[4 * BSTRIDE]);
            }
#pragma unroll
            for (int m = 0; m < 4; m++)
#pragma unroll
                for (int n = 0; n < 8; n++)
                    mma_tf32(acc[m][n], af[m], bf[n]);
        }
    }

    // epilogue: add bias, store
    {
        const float* brow = bias + (size_t)cat * N_DIM;
        float* obase = out + (size_t)batch * T_DIM * N_DIM;
#pragma unroll
        for (int m = 0; m < 4; m++) {
            int row = bm * TM + wm * 64 + m * 16 + fr;
#pragma unroll
            for (int n = 0; n < 8; n++) {
                int col = n0 + wn * 64 + n * 8 + fc * 2;
                float2 bv = *(const float2*)(brow + col);
                float2 o0, o1;
                o0.x = acc[m][n][0] + bv.x;
                o0.y = acc[m][n][1] + bv.y;
                o1.x = acc[m][n][2] + bv.x;
                o1.y = acc[m][n][3] + bv.y;
                *(float2*)(obase + (size_t)row * N_DIM + col)       = o0;
                *(float2*)(obase + (size_t)(row + 8) * N_DIM + col) = o1;
            }
        }
    }
}

extern "C" void kernel_launch(void* const* d_in, const int* in_sizes, int n_in,
                              void* d_out, int out_size)
{
    const float* x       = (const float*)d_in[0];
    const int*   cat_ids = (const int*)  d_in[1];
    const float* W       = (const float*)d_in[2];
    const float* bias    = (const float*)d_in[3];
    float*       out     = (float*)d_out;

    cudaFuncSetAttribute(cat_linear_mma, cudaFuncAttributeMaxDynamicSharedMemorySize, SMEM_BYTES);
    dim3 grid(N_DIM / TN, T_DIM / TM, B_DIM);   // (16, 2, 64)
    cat_linear_mma<<<grid, NTHREADS, SMEM_BYTES>>>(x, cat_ids, W, bias, out);
}

// round 6
// speedup vs baseline: 4.9431x; 1.5571x over previous
#include <cuda_runtime.h>
#include <cstdint>

// CategorySpecificLinear via mma.sync m16n8k16 fp16 (fp32 accumulate)
// + 3-stage cp.async pipeline. fp16 mantissa == tf32 mantissa (10 bits), and
// data range (x~N(0,1), W~0.02N(0,1)) is well inside fp16 range -> same
// accuracy as tf32 at 2x K-density per MMA instruction.
// out[b] = x[b] @ W[cat_ids[b]] + bias[cat_ids[b]]

#define B_DIM 64
#define T_DIM 256
#define K_DIM 1024
#define N_DIM 2048

#define TM 128
#define TN 128
#define TK 32
#define STAGES (K_DIM / TK)      // 32
#define NBUF 3
#define NTHREADS 128

#define ASTRIDE 40               // 32 k + 8 pad (floats): LDS.64 a-frags conflict-free
#define BSTRIDE 132              // 128 n + 4 pad (floats): scalar b-frags conflict-free
#define A_FLOATS (TM * ASTRIDE)  // 5120
#define B_FLOATS (TK * BSTRIDE)  // 4224
#define STAGE_FLOATS (A_FLOATS + B_FLOATS)     // 9344 (37376 B)
#define SMEM_BYTES (NBUF * STAGE_FLOATS * 4)   // 112128 -> 2 CTAs/SM

static __device__ __forceinline__ void cpasync16(uint32_t dst, const void* src) {
    asm volatile("cp.async.cg.shared.global [%0], [%1], 16;" :: "r"(dst), "l"(src));
}

// pack two f32 -> f16x2 (lo = first k, hi = second k)
static __device__ __forceinline__ uint32_t packh2(float lo, float hi) {
    uint32_t r;
    asm("cvt.rn.f16x2.f32 %0, %1, %2;" : "=r"(r) : "f"(hi), "f"(lo));
    return r;
}

static __device__ __forceinline__ void mma_f16(float (&d)[4],
                                               const uint32_t (&a)[4],
                                               const uint32_t (&b)[2]) {
    asm volatile(
        "mma.sync.aligned.m16n8k16.row.col.f32.f16.f16.f32 "
        "{%0,%1,%2,%3}, {%4,%5,%6,%7}, {%8,%9}, {%0,%1,%2,%3};"
        : "+f"(d[0]), "+f"(d[1]), "+f"(d[2]), "+f"(d[3])
        : "r"(a[0]), "r"(a[1]), "r"(a[2]), "r"(a[3]), "r"(b[0]), "r"(b[1]));
}

__global__ void __launch_bounds__(NTHREADS, 2)
cat_linear_mma(const float* __restrict__ x, const int* __restrict__ cat_ids,
               const float* __restrict__ W, const float* __restrict__ bias,
               float* __restrict__ out)
{
    extern __shared__ float sm[];
    const uint32_t smbase = (uint32_t)__cvta_generic_to_shared(sm);

    const int tid  = threadIdx.x;
    const int wid  = tid >> 5;
    const int lane = tid & 31;
    const int wm   = wid >> 1;        // 0..1  (M half)
    const int wn   = wid & 1;         // 0..1  (N half)
    const int fr   = lane >> 2;       // 0..7
    const int fc   = lane & 3;        // 0..3

    const int bn    = blockIdx.x;     // 0..15
    const int bm    = blockIdx.y;     // 0..1
    const int batch = blockIdx.z;     // 0..63
    const int n0    = bn * TN;
    const int cat   = cat_ids[batch];

    const float* Ap = x + (size_t)batch * T_DIM * K_DIM + (size_t)bm * TM * K_DIM;
    const float* Wp = W + (size_t)cat * K_DIM * N_DIM + n0;

    // cp.async mapping: 1024 16B chunks for A and for B, 8 each per thread
    int ar[8], ac[8], bk[8], bc[8];
#pragma unroll
    for (int i = 0; i < 8; i++) {
        int f = tid + NTHREADS * i;
        ar[i] = f >> 3;            // 0..127
        ac[i] = (f & 7) * 4;       // 0..28
        bk[i] = f >> 5;            // 0..31
        bc[i] = (f & 31) * 4;      // 0..124
    }

    float acc[4][8][4];
#pragma unroll
    for (int m = 0; m < 4; m++)
#pragma unroll
        for (int n = 0; n < 8; n++)
#pragma unroll
            for (int j = 0; j < 4; j++) acc[m][n][j] = 0.f;

    auto issue_stage = [&](int s, int buf) {
        const uint32_t abase = smbase + (uint32_t)(buf * STAGE_FLOATS) * 4u;
        const uint32_t bbase = abase + (uint32_t)A_FLOATS * 4u;
        const int k0 = s * TK;
#pragma unroll
        for (int i = 0; i < 8; i++)
            cpasync16(abase + (uint32_t)(ar[i] * ASTRIDE + ac[i]) * 4u,
                      Ap + (size_t)ar[i] * K_DIM + k0 + ac[i]);
#pragma unroll
        for (int i = 0; i < 8; i++)
            cpasync16(bbase + (uint32_t)(bk[i] * BSTRIDE + bc[i]) * 4u,
                      Wp + (size_t)(k0 + bk[i]) * N_DIM + bc[i]);
    };

    // prologue: stages 0,1 in flight
    issue_stage(0, 0);
    asm volatile("cp.async.commit_group;" ::: "memory");
    issue_stage(1, 1);
    asm volatile("cp.async.commit_group;" ::: "memory");

    for (int s = 0; s < STAGES; s++) {
        asm volatile("cp.async.wait_group 1;" ::: "memory");
        __syncthreads();

        if (s + 2 < STAGES)
            issue_stage(s + 2, (s + 2) % NBUF);
        asm volatile("cp.async.commit_group;" ::: "memory");

        const float* As = sm + (s % NBUF) * STAGE_FLOATS;
        const float* Bs = As + A_FLOATS;

#pragma unroll
        for (int kb = 0; kb < TK; kb += 16) {
            // ---- a-frags: LDS.64 pairs + f16x2 pack ----
            uint32_t af[4][4];
#pragma unroll
            for (int m = 0; m < 4; m++) {
                const float* ap0 = As + (wm * 64 + m * 16 + fr) * ASTRIDE + kb + fc * 2;
                const float* ap1 = ap0 + 8 * ASTRIDE;
                float2 v00 = *(const float2*)(ap0);       // k, k+1   row fr
                float2 v10 = *(const float2*)(ap1);       //          row fr+8
                float2 v01 = *(const float2*)(ap0 + 8);   // k+8, k+9 row fr
                float2 v11 = *(const float2*)(ap1 + 8);   //          row fr+8
                af[m][0] = packh2(v00.x, v00.y);
                af[m][1] = packh2(v10.x, v10.y);
                af[m][2] = packh2(v01.x, v01.y);
                af[m][3] = packh2(v11.x, v11.y);
            }
            // ---- b-frags: scalar LDS (k-major rows) + pack ----
            uint32_t bf[8][2];
#pragma unroll
            for (int n = 0; n < 8; n++) {
                const float* bp = Bs + (kb + fc * 2) * BSTRIDE + wn * 64 + n * 8 + fr;
                float b00 = bp[0];
                float b01 = bp[BSTRIDE];
                float b10 = bp[8 * BSTRIDE];
                float b11 = bp[9 * BSTRIDE];
                bf[n][0] = packh2(b00, b01);
                bf[n][1] = packh2(b10, b11);
            }
#pragma unroll
            for (int m = 0; m < 4; m++)
#pragma unroll
                for (int n = 0; n < 8; n++)
                    mma_f16(acc[m][n], af[m], bf[n]);
        }
    }

    // epilogue: add bias, store
    {
        const float* brow = bias + (size_t)cat * N_DIM;
        float* obase = out + (size_t)batch * T_DIM * N_DIM;
#pragma unroll
        for (int m = 0; m < 4; m++) {
            int row = bm * TM + wm * 64 + m * 16 + fr;
#pragma unroll
            for (int n = 0; n < 8; n++) {
                int col = n0 + wn * 64 + n * 8 + fc * 2;
                float2 bv = *(const float2*)(brow + col);
                float2 o0, o1;
                o0.x = acc[m][n][0] + bv.x;
                o0.y = acc[m][n][1] + bv.y;
                o1.x = acc[m][n][2] + bv.x;
                o1.y = acc[m][n][3] + bv.y;
                *(float2*)(obase + (size_t)row * N_DIM + col)       = o0;
                *(float2*)(obase + (size_t)(row + 8) * N_DIM + col) = o1;
            }
        }
    }
}

extern "C" void kernel_launch(void* const* d_in, const int* in_sizes, int n_in,
                              void* d_out, int out_size)
{
    const float* x       = (const float*)d_in[0];
    const int*   cat_ids = (const int*)  d_in[1];
    const float* W       = (const float*)d_in[2];
    const float* bias    = (const float*)d_in[3];
    float*       out     = (float*)d_out;

    cudaFuncSetAttribute(cat_linear_mma, cudaFuncAttributeMaxDynamicSharedMemorySize, SMEM_BYTES);
    dim3 grid(N_DIM / TN, T_DIM / TM, B_DIM);   // (16, 2, 64)
    cat_linear_mma<<<grid, NTHREADS, SMEM_BYTES>>>(x, cat_ids, W, bias, out);
}

// round 7
// speedup vs baseline: 5.4787x; 1.1084x over previous
#include <cuda_runtime.h>
#include <cstdint>

// CategorySpecificLinear: mma.sync m16n8k16 fp16 + fp16-in-smem + ldmatrix.
// Staging: LDG.128 fp32 -> cvt.rn.f16x2 -> STS.64 (double-buffered, reg prefetch).
// out[b] = x[b] @ W[cat_ids[b]] + bias[cat_ids[b]]

#define B_DIM 64
#define T_DIM 256
#define K_DIM 1024
#define N_DIM 2048

#define TM 128
#define TN 128
#define TK 32
#define STAGES (K_DIM / TK)      // 32
#define NTHREADS 128

// A tile: 128 rows x 32 k f16, 64B/row, 2 rows per 128B line, SW128 swizzle.
#define A_STAGE_BYTES (128 * 64)             // 8192
// B tile: 32 rows x 128 n f16, row = 256B + 16B pad = 272B.
#define B_ROW_BYTES 272
#define B_STAGE_BYTES (32 * B_ROW_BYTES)     // 8704
#define STAGE_BYTES (A_STAGE_BYTES + B_STAGE_BYTES)  // 16896
#define SMEM_BYTES (2 * STAGE_BYTES)         // 33792

// swizzle: byte ^ ((byte>>3)&0x70)  (for A only)
static __device__ __forceinline__ uint32_t sw(uint32_t b) { return b ^ ((b >> 3) & 0x70); }

static __device__ __forceinline__ uint32_t packh2(float lo, float hi) {
    uint32_t r;
    asm("cvt.rn.f16x2.f32 %0, %1, %2;" : "=r"(r) : "f"(hi), "f"(lo));
    return r;
}

static __device__ __forceinline__ void sts64(uint32_t addr, uint32_t w0, uint32_t w1) {
    asm volatile("st.shared.v2.b32 [%0], {%1,%2};" :: "r"(addr), "r"(w0), "r"(w1) : "memory");
}

static __device__ __forceinline__ void ldsm_x4(uint32_t (&r)[4], uint32_t addr) {
    asm volatile("ldmatrix.sync.aligned.m8n8.x4.shared.b16 {%0,%1,%2,%3}, [%4];"
                 : "=r"(r[0]), "=r"(r[1]), "=r"(r[2]), "=r"(r[3]) : "r"(addr));
}
static __device__ __forceinline__ void ldsm_x4_trans(uint32_t (&r)[4], uint32_t addr) {
    asm volatile("ldmatrix.sync.aligned.m8n8.x4.trans.shared.b16 {%0,%1,%2,%3}, [%4];"
                 : "=r"(r[0]), "=r"(r[1]), "=r"(r[2]), "=r"(r[3]) : "r"(addr));
}

static __device__ __forceinline__ void mma_f16(float (&d)[4],
                                               const uint32_t (&a)[4],
                                               const uint32_t* b) {
    asm volatile(
        "mma.sync.aligned.m16n8k16.row.col.f32.f16.f16.f32 "
        "{%0,%1,%2,%3}, {%4,%5,%6,%7}, {%8,%9}, {%0,%1,%2,%3};"
        : "+f"(d[0]), "+f"(d[1]), "+f"(d[2]), "+f"(d[3])
        : "r"(a[0]), "r"(a[1]), "r"(a[2]), "r"(a[3]), "r"(b[0]), "r"(b[1]));
}

__global__ void __launch_bounds__(NTHREADS, 2)
cat_linear_mma(const float* __restrict__ x, const int* __restrict__ cat_ids,
               const float* __restrict__ W, const float* __restrict__ bias,
               float* __restrict__ out)
{
    extern __shared__ char smraw[];
    const uint32_t smbase = (uint32_t)__cvta_generic_to_shared(smraw);

    const int tid  = threadIdx.x;
    const int wid  = tid >> 5;
    const int lane = tid & 31;
    const int wm   = wid >> 1;        // 0..1 (M half)
    const int wn   = wid & 1;         // 0..1 (N half)
    const int fr   = lane >> 2;       // 0..7
    const int fc   = lane & 3;        // 0..3

    const int bn    = blockIdx.x;     // 0..15
    const int bm    = blockIdx.y;     // 0..1
    const int batch = blockIdx.z;     // 0..63
    const int n0    = bn * TN;
    const int cat   = cat_ids[batch];

    const float* Ap = x + (size_t)batch * T_DIM * K_DIM + (size_t)bm * TM * K_DIM;
    const float* Wp = W + (size_t)cat * K_DIM * N_DIM + n0;

    // ---- staging maps ----
    // A: 1024 8B-chunks (m: 0..127, c: 0..7 -> k=4c). thread i covers
    //    m = (tid>>3)+16i, c = tid&7  -> LDG 128B rows, STS.64 conflict-free.
    const int am0 = tid >> 3;          // + 16*i
    const int ac  = tid & 7;
    // B: 1024 8B-chunks (k: 0..31, c: 0..31 -> n=4c). thread i covers
    //    k = (tid>>5)+4i, c = tid&31 -> LDG 512B rows, STS.64 consecutive.
    const int bk0 = tid >> 5;          // + 4*i
    const int bc  = tid & 31;

    // ---- ldmatrix per-lane address components ----
    const int q_row = (lane & 7) + 8 * ((lane >> 3) & 1);   // row within 16-block
    const int q_hi  = (lane >> 4);                           // 0/1: second 16B col
    // A: byte = SW( (wm*64 + mt*16 + q_row)*64 + kb*2 + 16*q_hi )
    const uint32_t a_pre = (uint32_t)((wm * 64 + q_row) * 64 + 16 * q_hi);
    // B: byte = (kb + q_row)*272 + (wn*64 + g*16 + 8*q_hi)*2
    const uint32_t b_pre = (uint32_t)(q_row * B_ROW_BYTES + (wn * 64 + 8 * q_hi) * 2);

    float acc[4][8][4];
#pragma unroll
    for (int m = 0; m < 4; m++)
#pragma unroll
        for (int n = 0; n < 8; n++)
#pragma unroll
            for (int j = 0; j < 4; j++) acc[m][n][j] = 0.f;

    float4 pa[8], pb[8];

    auto ldg_stage = [&](int k0) {
#pragma unroll
        for (int i = 0; i < 8; i++)
            pa[i] = *(const float4*)(Ap + (size_t)(am0 + 16 * i) * K_DIM + k0 + 4 * ac);
#pragma unroll
        for (int i = 0; i < 8; i++)
            pb[i] = *(const float4*)(Wp + (size_t)(k0 + bk0 + 4 * i) * N_DIM + 4 * bc);
    };

    auto sts_stage = [&](int buf) {
        const uint32_t abase = smbase + (uint32_t)buf * STAGE_BYTES;
        const uint32_t bbase = abase + A_STAGE_BYTES;
#pragma unroll
        for (int i = 0; i < 8; i++) {
            uint32_t byte = sw((uint32_t)(am0 + 16 * i) * 64u + (uint32_t)ac * 8u);
            sts64(abase + byte, packh2(pa[i].x, pa[i].y), packh2(pa[i].z, pa[i].w));
        }
#pragma unroll
        for (int i = 0; i < 8; i++) {
            uint32_t byte = (uint32_t)(bk0 + 4 * i) * B_ROW_BYTES + (uint32_t)bc * 8u;
            sts64(bbase + byte, packh2(pb[i].x, pb[i].y), packh2(pb[i].z, pb[i].w));
        }
    };

    // ---- prologue ----
    ldg_stage(0);
    sts_stage(0);
    __syncthreads();

    for (int s = 0; s < STAGES; s++) {
        if (s + 1 < STAGES)
            ldg_stage((s + 1) * TK);

        const uint32_t abase = smbase + (uint32_t)(s & 1) * STAGE_BYTES;
        const uint32_t bbase = abase + A_STAGE_BYTES;

#pragma unroll
        for (int kb = 0; kb < TK; kb += 16) {
            uint32_t af[4][4], bf[4][4];   // bf[g] covers n-groups 2g, 2g+1
#pragma unroll
            for (int mt = 0; mt < 4; mt++)
                ldsm_x4(af[mt], abase + sw(a_pre + (uint32_t)(mt * 16 * 64) + (uint32_t)(kb * 2)));
#pragma unroll
            for (int g = 0; g < 4; g++)
                ldsm_x4_trans(bf[g], bbase + b_pre + (uint32_t)(kb * B_ROW_BYTES) + (uint32_t)(g * 32));
#pragma unroll
            for (int m = 0; m < 4; m++)
#pragma unroll
                for (int n = 0; n < 8; n++)
                    mma_f16(acc[m][n], af[m], &bf[n >> 1][(n & 1) * 2]);
        }

        if (s + 1 < STAGES) {
            sts_stage((s + 1) & 1);
            __syncthreads();
        }
    }

    // ---- epilogue: add bias, store ----
    {
        const float* brow = bias + (size_t)cat * N_DIM;
        float* obase = out + (size_t)batch * T_DIM * N_DIM;
#pragma unroll
        for (int m = 0; m < 4; m++) {
            int row = bm * TM + wm * 64 + m * 16 + fr;
#pragma unroll
            for (int n = 0; n < 8; n++) {
                int col = n0 + wn * 64 + n * 8 + fc * 2;
                float2 bv = *(const float2*)(brow + col);
                float2 o0, o1;
                o0.x = acc[m][n][0] + bv.x;
                o0.y = acc[m][n][1] + bv.y;
                o1.x = acc[m][n][2] + bv.x;
                o1.y = acc[m][n][3] + bv.y;
                *(float2*)(obase + (size_t)row * N_DIM + col)       = o0;
                *(float2*)(obase + (size_t)(row + 8) * N_DIM + col) = o1;
            }
        }
    }
}

extern "C" void kernel_launch(void* const* d_in, const int* in_sizes, int n_in,
                              void* d_out, int out_size)
{
    const float* x       = (const float*)d_in[0];
    const int*   cat_ids = (const int*)  d_in[1];
    const float* W       = (const float*)d_in[2];
    const float* bias    = (const float*)d_in[3];
    float*       out     = (float*)d_out;

    cudaFuncSetAttribute(cat_linear_mma, cudaFuncAttributeMaxDynamicSharedMemorySize, SMEM_BYTES);
    dim3 grid(N_DIM / TN, T_DIM / TM, B_DIM);   // (16, 2, 64)
    cat_linear_mma<<<grid, NTHREADS, SMEM_BYTES>>>(x, cat_ids, W, bias, out);
}

// round 8
// speedup vs baseline: 5.7206x; 1.0442x over previous
#include <cuda_runtime.h>
#include <cuda_fp16.h>
#include <cstdint>

// CategorySpecificLinear, round 8:
//  pass 1/2: convert x and W to fp16 in __device__ scratch (bandwidth-bound)
//  pass 3:   GEMM: cp.async fp16 (L1-bypass) 4-stage ring + ldmatrix + mma f16
// out[b] = x[b] @ W[cat_ids[b]] + bias[cat_ids[b]]

#define B_DIM 64
#define T_DIM 256
#define K_DIM 1024
#define N_DIM 2048
#define NCAT  32

#define TM 128
#define TN 128
#define TK 32
#define STAGES (K_DIM / TK)      // 32
#define NBUF 4
#define NTHREADS 128

// A tile: 128 rows x 32 k f16 = 64B/row, SW128 swizzled.
#define A_STAGE_BYTES (128 * 64)             // 8192
// B tile: 32 k-rows x 128 n f16, row = 256B + 16B pad = 272B.
#define B_ROW_BYTES 272
#define B_STAGE_BYTES (32 * B_ROW_BYTES)     // 8704
#define STAGE_BYTES (A_STAGE_BYTES + B_STAGE_BYTES)  // 16896
#define SMEM_BYTES (NBUF * STAGE_BYTES)      // 67584

__device__ __half g_xh[(size_t)B_DIM * T_DIM * K_DIM];   // 32 MiB
__device__ __half g_wh[(size_t)NCAT * K_DIM * N_DIM];    // 128 MiB

static __device__ __forceinline__ uint32_t sw(uint32_t b) { return b ^ ((b >> 3) & 0x70); }

static __device__ __forceinline__ uint32_t packh2(float lo, float hi) {
    uint32_t r;
    asm("cvt.rn.f16x2.f32 %0, %1, %2;" : "=r"(r) : "f"(hi), "f"(lo));
    return r;
}

static __device__ __forceinline__ void cpasync16(uint32_t dst, const void* src) {
    asm volatile("cp.async.cg.shared.global [%0], [%1], 16;" :: "r"(dst), "l"(src));
}

static __device__ __forceinline__ void ldsm_x4(uint32_t (&r)[4], uint32_t addr) {
    asm volatile("ldmatrix.sync.aligned.m8n8.x4.shared.b16 {%0,%1,%2,%3}, [%4];"
                 : "=r"(r[0]), "=r"(r[1]), "=r"(r[2]), "=r"(r[3]) : "r"(addr));
}
static __device__ __forceinline__ void ldsm_x4_trans(uint32_t (&r)[4], uint32_t addr) {
    asm volatile("ldmatrix.sync.aligned.m8n8.x4.trans.shared.b16 {%0,%1,%2,%3}, [%4];"
                 : "=r"(r[0]), "=r"(r[1]), "=r"(r[2]), "=r"(r[3]) : "r"(addr));
}

static __device__ __forceinline__ void mma_f16(float (&d)[4],
                                               const uint32_t (&a)[4],
                                               const uint32_t* b) {
    asm volatile(
        "mma.sync.aligned.m16n8k16.row.col.f32.f16.f16.f32 "
        "{%0,%1,%2,%3}, {%4,%5,%6,%7}, {%8,%9}, {%0,%1,%2,%3};"
        : "+f"(d[0]), "+f"(d[1]), "+f"(d[2]), "+f"(d[3])
        : "r"(a[0]), "r"(a[1]), "r"(a[2]), "r"(a[3]), "r"(b[0]), "r"(b[1]));
}

// ---------------- converter: fp32 -> fp16, 8 elems per thread-iter ----------
__global__ void __launch_bounds__(256)
cvt_f32_f16(const float* __restrict__ src, __half* __restrict__ dst, int n8)
{
    int i = blockIdx.x * blockDim.x + threadIdx.x;
    const int stride = gridDim.x * blockDim.x;
    for (; i < n8; i += stride) {
        float4 a = ((const float4*)src)[2 * i];
        float4 b = ((const float4*)src)[2 * i + 1];
        uint4 o;
        o.x = packh2(a.x, a.y);
        o.y = packh2(a.z, a.w);
        o.z = packh2(b.x, b.y);
        o.w = packh2(b.z, b.w);
        ((uint4*)dst)[i] = o;
    }
}

// ---------------- GEMM ------------------------------------------------------
__global__ void __launch_bounds__(NTHREADS, 2)
cat_linear_mma(const int* __restrict__ cat_ids,
               const float* __restrict__ bias,
               float* __restrict__ out)
{
    extern __shared__ char smraw[];
    const uint32_t smbase = (uint32_t)__cvta_generic_to_shared(smraw);

    const int tid  = threadIdx.x;
    const int wid  = tid >> 5;
    const int lane = tid & 31;
    const int wm   = wid >> 1;        // 0..1 (M half)
    const int wn   = wid & 1;         // 0..1 (N half)
    const int fr   = lane >> 2;       // 0..7
    const int fc   = lane & 3;        // 0..3

    const int bn    = blockIdx.x;     // 0..15
    const int bm    = blockIdx.y;     // 0..1
    const int batch = blockIdx.z;     // 0..63
    const int n0    = bn * TN;
    const int cat   = cat_ids[batch];

    const __half* Ap = g_xh + (size_t)batch * T_DIM * K_DIM + (size_t)bm * TM * K_DIM;
    const __half* Bp = g_wh + (size_t)cat * K_DIM * N_DIM + n0;

    // cp.async maps (16B granules):
    // A: 512 chunks = 128 rows x 4; thread: m=(tid>>2)+32i, c=tid&3
    const int am0 = tid >> 2;
    const int acx = tid & 3;
    // B: 512 chunks = 32 rows x 16; thread: k=(tid>>4)+8i, c=tid&15
    const int bk0 = tid >> 4;
    const int bcx = tid & 15;

    // ldmatrix per-lane address components (identical to round-7 mapping)
    const int q_row = (lane & 7) + 8 * ((lane >> 3) & 1);
    const int q_hi  = (lane >> 4);
    const uint32_t a_pre = (uint32_t)((wm * 64 + q_row) * 64 + 16 * q_hi);
    const uint32_t b_pre = (uint32_t)(q_row * B_ROW_BYTES + (wn * 64 + 8 * q_hi) * 2);

    float acc[4][8][4];
#pragma unroll
    for (int m = 0; m < 4; m++)
#pragma unroll
        for (int n = 0; n < 8; n++)
#pragma unroll
            for (int j = 0; j < 4; j++) acc[m][n][j] = 0.f;

    auto issue_stage = [&](int s, int buf) {
        const uint32_t abase = smbase + (uint32_t)buf * STAGE_BYTES;
        const uint32_t bbase = abase + A_STAGE_BYTES;
        const int k0 = s * TK;
#pragma unroll
        for (int i = 0; i < 4; i++) {
            int m = am0 + 32 * i;
            cpasync16(abase + sw((uint32_t)m * 64u + (uint32_t)acx * 16u),
                      Ap + (size_t)m * K_DIM + k0 + acx * 8);
        }
#pragma unroll
        for (int i = 0; i < 4; i++) {
            int k = bk0 + 8 * i;
            cpasync16(bbase + (uint32_t)k * B_ROW_BYTES + (uint32_t)bcx * 16u,
                      Bp + (size_t)(k0 + k) * N_DIM + bcx * 8);
        }
    };

    // prologue: 3 stages in flight
    issue_stage(0, 0);
    asm volatile("cp.async.commit_group;" ::: "memory");
    issue_stage(1, 1);
    asm volatile("cp.async.commit_group;" ::: "memory");
    issue_stage(2, 2);
    asm volatile("cp.async.commit_group;" ::: "memory");

    for (int s = 0; s < STAGES; s++) {
        asm volatile("cp.async.wait_group 2;" ::: "memory");
        __syncthreads();

        // refill: buffer (s+3)%4 held stage s-1, finished by all warps at the barrier
        if (s + 3 < STAGES)
            issue_stage(s + 3, (s + 3) % NBUF);
        asm volatile("cp.async.commit_group;" ::: "memory");

        const uint32_t abase = smbase + (uint32_t)(s % NBUF) * STAGE_BYTES;
        const uint32_t bbase = abase + A_STAGE_BYTES;

#pragma unroll
        for (int kb = 0; kb < TK; kb += 16) {
            uint32_t af[4][4], bf[4][4];
#pragma unroll
            for (int mt = 0; mt < 4; mt++)
                ldsm_x4(af[mt], abase + sw(a_pre + (uint32_t)(mt * 16 * 64) + (uint32_t)(kb * 2)));
#pragma unroll
            for (int g = 0; g < 4; g++)
                ldsm_x4_trans(bf[g], bbase + b_pre + (uint32_t)(kb * B_ROW_BYTES) + (uint32_t)(g * 32));
#pragma unroll
            for (int m = 0; m < 4; m++)
#pragma unroll
                for (int n = 0; n < 8; n++)
                    mma_f16(acc[m][n], af[m], &bf[n >> 1][(n & 1) * 2]);
        }
    }

    // epilogue: add bias, store
    {
        const float* brow = bias + (size_t)cat * N_DIM;
        float* obase = out + (size_t)batch * T_DIM * N_DIM;
#pragma unroll
        for (int m = 0; m < 4; m++) {
            int row = bm * TM + wm * 64 + m * 16 + fr;
#pragma unroll
            for (int n = 0; n < 8; n++) {
                int col = n0 + wn * 64 + n * 8 + fc * 2;
                float2 bv = *(const float2*)(brow + col);
                float2 o0, o1;
                o0.x = acc[m][n][0] + bv.x;
                o0.y = acc[m][n][1] + bv.y;
                o1.x = acc[m][n][2] + bv.x;
                o1.y = acc[m][n][3] + bv.y;
                *(float2*)(obase + (size_t)row * N_DIM + col)       = o0;
                *(float2*)(obase + (size_t)(row + 8) * N_DIM + col) = o1;
            }
        }
    }
}

extern "C" void kernel_launch(void* const* d_in, const int* in_sizes, int n_in,
                              void* d_out, int out_size)
{
    const float* x       = (const float*)d_in[0];
    const int*   cat_ids = (const int*)  d_in[1];
    const float* W       = (const float*)d_in[2];
    const float* bias    = (const float*)d_in[3];
    float*       out     = (float*)d_out;

    __half* xh = nullptr; __half* wh = nullptr;
    cudaGetSymbolAddress((void**)&xh, g_xh);
    cudaGetSymbolAddress((void**)&wh, g_wh);

    // pass 1+2: fp32 -> fp16 converters
    {
        int n8x = (B_DIM * T_DIM * K_DIM) / 8;          // 2,097,152
        int n8w = (NCAT * K_DIM * N_DIM) / 8;           // 8,388,608
        cvt_f32_f16<<<2048, 256>>>(x, xh, n8x);
        cvt_f32_f16<<<4096, 256>>>(W, wh, n8w);
    }

    // pass 3: GEMM
    cudaFuncSetAttribute(cat_linear_mma, cudaFuncAttributeMaxDynamicSharedMemorySize, SMEM_BYTES);
    dim3 grid(N_DIM / TN, T_DIM / TM, B_DIM);   // (16, 2, 64)
    cat_linear_mma<<<grid, NTHREADS, SMEM_BYTES>>>(cat_ids, bias, out);
}